// round 7
// baseline (speedup 1.0000x reference)
#include <cuda_runtime.h>
#include <cuda_fp16.h>
#include <cstdint>

#define BB 32
#define NN 2048
#define CIN 64
#define COUTC 128
#define ADJ_EPS 1e-6f
#define BN_EPS 1e-5f

// smem geometry (uint32 words; fp16 data packed as half2)
#define SAP 20                 // xh tile row stride (words); banks (ar*20+ac)%32 all distinct
#define SBP 136                // Ah tile row stride (words); banks (ac*8+ar)%32 all distinct
#define SA_BYTES (64 * SAP * 4)          // 5120
#define SB_BYTES (16 * SBP * 4)          // 8704
#define STAGE_BYTES (SA_BYTES + SB_BYTES)  // 13824 (16B-multiple)
#define NSTAGE 3
#define SMEM_BYTES (NSTAGE * STAGE_BYTES)  // 41472 (>= 34816 epilogue floats)

// ---------------- scratch (device globals; no allocations allowed) ----------
__device__ uint32_t g_Ah[(size_t)BB * 1024 * NN];   // 268MB: half2{A[2r][m]*inv0, A[2r+1][m]*inv1}
__device__ uint32_t g_xh[(size_t)BB * 64 * 1024];   // 8MB:  half2{x[2n][c], x[2n+1][c]} as [c][np]
__device__ float g_h[(size_t)BB * NN * COUTC];      // pre-BN activations [b][m][o]
__device__ float g_stats[2 * COUTC];

__device__ __forceinline__ uint32_t smem_u32(const void* p) {
    uint32_t a;
    asm("{ .reg .u64 t; cvta.to.shared.u64 t, %1; cvt.u32.u64 %0, t; }" : "=r"(a) : "l"(p));
    return a;
}
__device__ __forceinline__ void cp16(uint32_t dst, const void* src) {
    asm volatile("cp.async.cg.shared.global [%0], [%1], 16;" :: "r"(dst), "l"(src));
}
__device__ __forceinline__ uint32_t pack2(float lo, float hi) {
    __half2 h = __floats2half2_rn(lo, hi);
    return *reinterpret_cast<uint32_t*>(&h);
}

// ---------------------------------------------------------------------------
// K1: row sums + fp16 convert of A, one warp per row-PAIR.
// Writes g_Ah[b*1024+r][m] = half2{ A[b][2r][m]*invS(2r), A[b][2r+1][m]*invS(2r+1) }
// Second read of the rows hits L1 (16KB/warp resident).
// ---------------------------------------------------------------------------
__global__ void k_rowcvt(const float* __restrict__ A) {
    if (blockIdx.x == 0 && threadIdx.x < 2 * COUTC) g_stats[threadIdx.x] = 0.f;
    int task = blockIdx.x * (blockDim.x >> 5) + (threadIdx.x >> 5);
    int lane = threadIdx.x & 31;
    if (task >= BB * 1024) return;
    const float4* r0 = reinterpret_cast<const float4*>(A + (size_t)task * 2 * NN);
    const float4* r1 = reinterpret_cast<const float4*>(A + (size_t)task * 2 * NN + NN);
    float s0 = 0.f, s1 = 0.f;
#pragma unroll 4
    for (int i = lane; i < NN / 4; i += 32) {
        float4 a = r0[i]; s0 += a.x + a.y + a.z + a.w;
        float4 b = r1[i]; s1 += b.x + b.y + b.z + b.w;
    }
#pragma unroll
    for (int o = 16; o; o >>= 1) {
        s0 += __shfl_xor_sync(0xFFFFFFFFu, s0, o);
        s1 += __shfl_xor_sync(0xFFFFFFFFu, s1, o);
    }
    float inv0 = 1.0f / (s0 + ADJ_EPS), inv1 = 1.0f / (s1 + ADJ_EPS);
    uint4* dst = reinterpret_cast<uint4*>(g_Ah + (size_t)task * NN);
#pragma unroll 4
    for (int i = lane; i < NN / 4; i += 32) {
        float4 a = r0[i], b = r1[i];
        uint4 o;
        o.x = pack2(a.x * inv0, b.x * inv1);
        o.y = pack2(a.y * inv0, b.y * inv1);
        o.z = pack2(a.z * inv0, b.z * inv1);
        o.w = pack2(a.w * inv0, b.w * inv1);
        dst[i] = o;
    }
}

// ---------------------------------------------------------------------------
// K1b: g_xh[b][c][np] = half2{x[b][2np][c], x[b][2np+1][c]} (transpose via smem)
// ---------------------------------------------------------------------------
__global__ void __launch_bounds__(256) k_prep(const float* __restrict__ x) {
    __shared__ float sx[64 * 65];
    const int b = blockIdx.y, n0 = blockIdx.x * 64, tid = threadIdx.x;
#pragma unroll
    for (int l = 0; l < 4; l++) {
        int i = tid + 256 * l;
        int n = i >> 4, c4 = i & 15;
        float4 v = *reinterpret_cast<const float4*>(x + ((size_t)b * NN + n0 + n) * 64 + c4 * 4);
        sx[n * 65 + c4 * 4 + 0] = v.x;
        sx[n * 65 + c4 * 4 + 1] = v.y;
        sx[n * 65 + c4 * 4 + 2] = v.z;
        sx[n * 65 + c4 * 4 + 3] = v.w;
    }
    __syncthreads();
#pragma unroll
    for (int l = 0; l < 8; l++) {
        int i = tid + 256 * l;
        int c = i >> 5, np = i & 31;
        g_xh[(size_t)(b * 64 + c) * 1024 + n0 / 2 + np] =
            pack2(sx[(2 * np) * 65 + c], sx[(2 * np + 1) * 65 + c]);
    }
}

// ---------------------------------------------------------------------------
// K2: fp16 mma.m16n8k16 GEMM + fused 1x1 conv + BN stats.
// Per CTA: D[c(64), m(128)] = sum_n xh[c][n] * Ah[n][m0+m], K = 2048.
// 3-stage cp.async ring (768 cp16/chunk), fragments from packed-half2 smem.
// ---------------------------------------------------------------------------
__global__ void __launch_bounds__(256, 2) k_gemm(const float* __restrict__ Wm,
                                                 const float* __restrict__ bias) {
    extern __shared__ float sm[];
    __shared__ float s_sum[COUTC], s_sq[COUTC];

    const uint32_t smb = smem_u32(sm);
    const int tid = threadIdx.x;
    const int w = tid >> 5, lane = tid & 31;
    const int bb = blockIdx.y, m0 = blockIdx.x * 128;
    const uint32_t* Ahb = g_Ah + (size_t)bb * 1024 * NN;
    const uint32_t* xhb = g_xh + (size_t)bb * 64 * 1024;

    float acc[4][2][4];
#pragma unroll
    for (int mt = 0; mt < 4; mt++)
#pragma unroll
        for (int nt = 0; nt < 2; nt++)
#pragma unroll
            for (int j = 0; j < 4; j++) acc[mt][nt][j] = 0.f;

    // per-thread load coords (constant): A-op 1 cp16, B-op 2 cp16
    const int la_c = tid >> 2, la_q = tid & 3;
    const int lb_k = tid >> 5, lb_q = tid & 31;

    auto issue = [&](int ch, uint32_t sa) {
        const int np0 = ch * 16;   // 16 half2-pairs = 32 k per chunk
        const uint32_t sb = sa + SA_BYTES;
        cp16(sa + la_c * (SAP * 4) + la_q * 16, xhb + (size_t)la_c * 1024 + np0 + la_q * 4);
#pragma unroll
        for (int l = 0; l < 2; l++)
            cp16(sb + (lb_k + 8 * l) * (SBP * 4) + lb_q * 16,
                 Ahb + (size_t)(np0 + lb_k + 8 * l) * NN + m0 + lb_q * 4);
    };

    issue(0, smb);
    asm volatile("cp.async.commit_group;");
    issue(1, smb + STAGE_BYTES);
    asm volatile("cp.async.commit_group;");

    const int ar = lane >> 2, ac = lane & 3;

    for (int ch = 0; ch < 64; ch++) {
        const int s = ch % NSTAGE;
        asm volatile("cp.async.wait_group 1;");
        __syncthreads();

        const uint32_t* sA = reinterpret_cast<const uint32_t*>(
            reinterpret_cast<const char*>(sm) + s * STAGE_BYTES);
        const uint32_t* sB = sA + SA_BYTES / 4;

#pragma unroll
        for (int ks = 0; ks < 2; ks++) {
            uint32_t a[4][4];
#pragma unroll
            for (int mt = 0; mt < 4; mt++) {
                const uint32_t* b0 = sA + (mt * 16 + ar) * SAP + ks * 8 + ac;
                const uint32_t* b1 = sA + (mt * 16 + ar + 8) * SAP + ks * 8 + ac;
                a[mt][0] = b0[0];
                a[mt][1] = b1[0];
                a[mt][2] = b0[4];
                a[mt][3] = b1[4];
            }
            uint32_t b[2][2];
#pragma unroll
            for (int nt = 0; nt < 2; nt++) {
                const uint32_t* base = sB + (ks * 8 + ac) * SBP + w * 16 + nt * 8 + ar;
                b[nt][0] = base[0];
                b[nt][1] = base[4 * SBP];
            }
#pragma unroll
            for (int mt = 0; mt < 4; mt++)
#pragma unroll
                for (int nt = 0; nt < 2; nt++)
                    asm volatile(
                        "mma.sync.aligned.m16n8k16.row.col.f32.f16.f16.f32 "
                        "{%0,%1,%2,%3}, {%4,%5,%6,%7}, {%8,%9}, {%0,%1,%2,%3};"
                        : "+f"(acc[mt][nt][0]), "+f"(acc[mt][nt][1]),
                          "+f"(acc[mt][nt][2]), "+f"(acc[mt][nt][3])
                        : "r"(a[mt][0]), "r"(a[mt][1]), "r"(a[mt][2]), "r"(a[mt][3]),
                          "r"(b[nt][0]), "r"(b[nt][1]));
        }

        __syncthreads();   // all warps done with stage of chunk ch-1's slot
        if (ch + 2 < 64) issue(ch + 2, smb + ((ch + 2) % NSTAGE) * STAGE_BYTES);
        asm volatile("cp.async.commit_group;");
    }
    __syncthreads();   // compute done before smem reuse for xg

    // ---- accumulators -> smem xg[m][68 stride] (conflict-free scatter) ----
#pragma unroll
    for (int mt = 0; mt < 4; mt++)
#pragma unroll
        for (int nt = 0; nt < 2; nt++) {
            int cr = mt * 16 + (lane >> 2);
            int mc = w * 16 + nt * 8 + 2 * (lane & 3);
            sm[mc * 68 + cr]           = acc[mt][nt][0];
            sm[(mc + 1) * 68 + cr]     = acc[mt][nt][1];
            sm[mc * 68 + cr + 8]       = acc[mt][nt][2];
            sm[(mc + 1) * 68 + cr + 8] = acc[mt][nt][3];
        }
    if (tid < COUTC) { s_sum[tid] = 0.f; s_sq[tid] = 0.f; }
    __syncthreads();

    // ---- epilogue: h = xg @ W^T + bias, BN stats, store h ----
    const float4* W4 = reinterpret_cast<const float4*>(Wm);
    const int tx = tid & 15, ty = tid >> 4;
#pragma unroll
    for (int op = 0; op < 4; op++) {
        int o0 = tx * 8 + op * 2;
        float h0[8], h1[8];
#pragma unroll
        for (int mi = 0; mi < 8; mi++) { h0[mi] = 0.f; h1[mi] = 0.f; }
#pragma unroll
        for (int c4 = 0; c4 < 16; c4++) {
            float4 w0 = W4[(size_t)o0 * 16 + c4];
            float4 w1 = W4[(size_t)(o0 + 1) * 16 + c4];
#pragma unroll
            for (int mi = 0; mi < 8; mi++) {
                float4 g = *reinterpret_cast<const float4*>(&sm[(ty * 8 + mi) * 68 + c4 * 4]);
                h0[mi] += g.x * w0.x + g.y * w0.y + g.z * w0.z + g.w * w0.w;
                h1[mi] += g.x * w1.x + g.y * w1.y + g.z * w1.z + g.w * w1.w;
            }
        }
        float b0 = bias[o0], b1 = bias[o0 + 1];
        float sA2 = 0.f, qA = 0.f, sB2 = 0.f, qB = 0.f;
        size_t base = ((size_t)bb * NN + m0 + ty * 8) * COUTC + o0;
#pragma unroll
        for (int mi = 0; mi < 8; mi++) {
            float v0 = h0[mi] + b0, v1 = h1[mi] + b1;
            sA2 += v0; qA += v0 * v0;
            sB2 += v1; qB += v1 * v1;
            *reinterpret_cast<float2*>(&g_h[base + (size_t)mi * COUTC]) = make_float2(v0, v1);
        }
        atomicAdd(&s_sum[o0], sA2);     atomicAdd(&s_sq[o0], qA);
        atomicAdd(&s_sum[o0 + 1], sB2); atomicAdd(&s_sq[o0 + 1], qB);
    }
    __syncthreads();
    if (tid < COUTC)          atomicAdd(&g_stats[tid], s_sum[tid]);
    else if (tid < 2 * COUTC) atomicAdd(&g_stats[tid], s_sq[tid - COUTC]);
}

// ---------------------------------------------------------------------------
// K3: BN finalize + ReLU (g_h layout == output layout)
// ---------------------------------------------------------------------------
__global__ void k_bn(float* __restrict__ out,
                     const float* __restrict__ gamma,
                     const float* __restrict__ beta) {
    __shared__ float s_scale[COUTC], s_shift[COUTC];
    if (threadIdx.x < COUTC) {
        int o = threadIdx.x;
        float cnt = (float)(BB * NN);
        float mean = g_stats[o] / cnt;
        float var = g_stats[o + COUTC] / cnt - mean * mean;
        float sc = gamma[o] * rsqrtf(var + BN_EPS);
        s_scale[o] = sc;
        s_shift[o] = beta[o] - mean * sc;
    }
    __syncthreads();
    const size_t total = (size_t)BB * NN * COUTC / 4;
    const float4* h4 = reinterpret_cast<const float4*>(g_h);
    float4* o4 = reinterpret_cast<float4*>(out);
    for (size_t idx = (size_t)blockIdx.x * blockDim.x + threadIdx.x; idx < total;
         idx += (size_t)gridDim.x * blockDim.x) {
        float4 v = h4[idx];
        int o = ((int)idx & 31) * 4;
        v.x = fmaxf(fmaf(v.x, s_scale[o + 0], s_shift[o + 0]), 0.f);
        v.y = fmaxf(fmaf(v.y, s_scale[o + 1], s_shift[o + 1]), 0.f);
        v.z = fmaxf(fmaf(v.z, s_scale[o + 2], s_shift[o + 2]), 0.f);
        v.w = fmaxf(fmaf(v.w, s_scale[o + 3], s_shift[o + 3]), 0.f);
        o4[idx] = v;
    }
}

extern "C" void kernel_launch(void* const* d_in, const int* in_sizes, int n_in,
                              void* d_out, int out_size) {
    const float* x     = (const float*)d_in[0];
    const float* A     = (const float*)d_in[1];
    const float* W     = (const float*)d_in[2];
    const float* bias  = (const float*)d_in[3];
    const float* gamma = (const float*)d_in[4];
    const float* beta  = (const float*)d_in[5];
    float* out = (float*)d_out;

    cudaFuncSetAttribute(k_gemm, cudaFuncAttributeMaxDynamicSharedMemorySize, SMEM_BYTES);

    k_rowcvt<<<BB * 1024 / 8, 256>>>(A);
    dim3 gp(NN / 64, BB);
    k_prep<<<gp, 256>>>(x);
    dim3 g2(NN / 128, BB);
    k_gemm<<<g2, 256, SMEM_BYTES>>>(W, bias);
    k_bn<<<4096, 256>>>(out, gamma, beta);
}